// round 7
// baseline (speedup 1.0000x reference)
#include <cuda_runtime.h>
#include <cuda_bf16.h>
#include <cstdint>

#define BB   4
#define NP   8192
#define SP   2048
#define D1   128
#define D2   256
#define CIN  384
#define COUT 256
#define RSI  384          // input concat row stride [n][c]
#define RSB  256          // post-fuse buffer row stride [n][c]
#define BN_EPS 1e-5f

#define BM   128
#define BN   64
#define BKc  32
#define SST  40           // smem row stride in bf16 (80 B, conflict-free for ldmatrix)
#define NSLOT 512

#define WTOT   (COUT * CIN + 4 * COUT * COUT)
#define OFF_W1 (COUT * CIN)
#define OFF_W2 (OFF_W1 + 2 * COUT * COUT)
#define CC     (COUT * COUT)

// ---------------- scratch ----------------
__device__ float g_p2t[BB * SP * D2];
__device__ float g_t  [(size_t)BB * COUT * NP];          // fp32 t (blk2 outputs only)
__device__ __nv_bfloat16 g_bth[(size_t)BB * NP * RSI];   // input concat [n][384]; later trunk [n][256]
__device__ __nv_bfloat16 g_btl[(size_t)BB * NP * RSI];
__device__ __nv_bfloat16 g_tfh[(size_t)BB * NP * RSB];   // raw t_fuse pair [n][256]
__device__ __nv_bfloat16 g_tfl[(size_t)BB * NP * RSB];
__device__ __nv_bfloat16 g_byh[(size_t)BB * NP * RSB];   // raw t1 pair [n][256]
__device__ __nv_bfloat16 g_byl[(size_t)BB * NP * RSB];
__device__ __nv_bfloat16 g_wh[WTOT];
__device__ __nv_bfloat16 g_wl[WTOT];
__device__ float g_psum[COUT * NSLOT];
__device__ float g_psq [COUT * NSLOT];
__device__ int   g_idx[BB * NP * 3];
__device__ float g_w  [BB * NP * 3];
__device__ float g_na [5 * COUT];                        // per-layer BN scale slots
__device__ float g_nb [5 * COUT];

__device__ __forceinline__ void bf16_split(float v, __nv_bfloat16& hi, __nv_bfloat16& lo) {
    hi = __float2bfloat16(v);
    lo = __float2bfloat16(v - __bfloat162float(hi));
}
__device__ __forceinline__ uint32_t smem_u32(const void* p) {
    uint32_t a;
    asm("{ .reg .u64 t; cvta.to.shared.u64 t, %1; cvt.u32.u64 %0, t; }" : "=r"(a) : "l"(p));
    return a;
}
__device__ __forceinline__ void mma16816(float* c, const uint32_t* a, const uint32_t* b) {
    asm volatile(
        "mma.sync.aligned.m16n8k16.row.col.f32.bf16.bf16.f32 "
        "{%0,%1,%2,%3}, {%4,%5,%6,%7}, {%8,%9}, {%0,%1,%2,%3};"
        : "+f"(c[0]), "+f"(c[1]), "+f"(c[2]), "+f"(c[3])
        : "r"(a[0]), "r"(a[1]), "r"(a[2]), "r"(a[3]), "r"(b[0]), "r"(b[1]));
}
__device__ __forceinline__ void ldsm4(uint32_t* r, uint32_t addr) {
    asm volatile("ldmatrix.sync.aligned.m8n8.x4.shared.b16 {%0,%1,%2,%3}, [%4];"
        : "=r"(r[0]), "=r"(r[1]), "=r"(r[2]), "=r"(r[3]) : "r"(addr));
}
__device__ __forceinline__ void cp16(uint32_t daddr, const void* src) {
    asm volatile("cp.async.cg.shared.global [%0], [%1], 16;" :: "r"(daddr), "l"(src));
}

// ---------------- KNN ----------------
__global__ void __launch_bounds__(128) knn_kernel(const float* __restrict__ xyz1,
                                                  const float* __restrict__ xyz2) {
    __shared__ float sx[SP], sy[SP], sz[SP], sn[SP];
    int b = blockIdx.y;
    const float* x2 = xyz2 + (size_t)b * 3 * SP;
    for (int i = threadIdx.x; i < SP; i += 128) {
        float X = x2[i], Y = x2[SP + i], Z = x2[2 * SP + i];
        sx[i] = X; sy[i] = Y; sz[i] = Z; sn[i] = X * X + Y * Y + Z * Z;
    }
    __syncthreads();
    int n = blockIdx.x * 128 + threadIdx.x;
    const float* x1 = xyz1 + (size_t)b * 3 * NP;
    float qx = x1[n], qy = x1[NP + n], qz = x1[2 * NP + n];
    float qn = qx * qx + qy * qy + qz * qz;

    float d0 = 3.4e38f, d1 = 3.4e38f, d2v = 3.4e38f;
    int i0 = 0, i1 = 0, i2 = 0;
#pragma unroll 4
    for (int s = 0; s < SP; s++) {
        float dot = qx * sx[s] + qy * sy[s] + qz * sz[s];
        float d = qn + sn[s] - 2.0f * dot;
        if (d < d2v) {
            if (d < d1) {
                d2v = d1; i2 = i1;
                if (d < d0) { d1 = d0; i1 = i0; d0 = d; i0 = s; }
                else        { d1 = d;  i1 = s; }
            } else { d2v = d; i2 = s; }
        }
    }
    float r0 = 1.0f / (d0 + 1e-8f);
    float r1 = 1.0f / (d1 + 1e-8f);
    float r2 = 1.0f / (d2v + 1e-8f);
    float inv = 1.0f / (r0 + r1 + r2);
    size_t base = ((size_t)b * NP + n) * 3;
    g_idx[base] = i0; g_idx[base + 1] = i1; g_idx[base + 2] = i2;
    g_w[base] = r0 * inv; g_w[base + 1] = r1 * inv; g_w[base + 2] = r2 * inv;
}

// ---------------- transpose points2 [b][c][s] -> [b][s][c] ----------------
__global__ void transpose_p2_kernel(const float* __restrict__ p2) {
    __shared__ float tile[32][33];
    int b = blockIdx.z;
    int s0 = blockIdx.x * 32, c0 = blockIdx.y * 32;
    int tx = threadIdx.x, ty = threadIdx.y;
#pragma unroll
    for (int j = 0; j < 32; j += 8)
        tile[ty + j][tx] = p2[((size_t)b * D2 + c0 + ty + j) * SP + s0 + tx];
    __syncthreads();
    float* dst = g_p2t + (size_t)b * SP * D2;
#pragma unroll
    for (int j = 0; j < 32; j += 8)
        dst[(size_t)(s0 + ty + j) * D2 + c0 + tx] = tile[tx][ty + j];
}

// ---------------- interp: concat rows [n][128..383] ----------------
__global__ void __launch_bounds__(256) interp_kernel() {
    __shared__ float sw[32][3];
    __shared__ int   si[32][3];
    int b = blockIdx.y;
    int n0 = blockIdx.x * 32;
    int tid = threadIdx.x;
    if (tid < 96) {
        int q = tid / 3, k = tid % 3;
        size_t base = ((size_t)b * NP + n0 + q) * 3 + k;
        sw[q][k] = g_w[base];
        si[q][k] = g_idx[base];
    }
    __syncthreads();
    const float* f2 = g_p2t + (size_t)b * SP * D2;
    int c = tid;
#pragma unroll 4
    for (int q = 0; q < 32; q++) {
        float v = sw[q][0] * f2[(size_t)si[q][0] * D2 + c]
                + sw[q][1] * f2[(size_t)si[q][1] * D2 + c]
                + sw[q][2] * f2[(size_t)si[q][2] * D2 + c];
        __nv_bfloat16 hi, lo;
        bf16_split(v, hi, lo);
        size_t o = ((size_t)b * NP + n0 + q) * RSI + D1 + c;
        g_bth[o] = hi;
        g_btl[o] = lo;
    }
}

// ---------------- points1 -> concat rows [n][0..127] ----------------
__global__ void convert_p1_kernel(const float* __restrict__ p1) {
    __shared__ float tile[32][33];
    int b = blockIdx.z;
    int n0 = blockIdx.x * 32, c0 = blockIdx.y * 32;
    int tx = threadIdx.x, ty = threadIdx.y;
#pragma unroll
    for (int j = 0; j < 32; j += 8)
        tile[ty + j][tx] = p1[((size_t)b * D1 + c0 + ty + j) * NP + n0 + tx];
    __syncthreads();
#pragma unroll
    for (int j = 0; j < 32; j += 8) {
        float v = tile[tx][ty + j];
        __nv_bfloat16 hi, lo;
        bf16_split(v, hi, lo);
        size_t o = ((size_t)b * NP + n0 + ty + j) * RSI + c0 + tx;
        g_bth[o] = hi;
        g_btl[o] = lo;
    }
}

// ---------------- all weights fp32 -> bf16 hi/lo ----------------
__global__ void convert_w_all_kernel(const float* __restrict__ fw,
                                     const float* __restrict__ w1,
                                     const float* __restrict__ w2) {
    int i = blockIdx.x * 256 + threadIdx.x;
    if (i >= WTOT) return;
    float v;
    if (i < OFF_W1)      v = fw[i];
    else if (i < OFF_W2) v = w1[i - OFF_W1];
    else                 v = w2[i - OFF_W2];
    __nv_bfloat16 hi, lo;
    bf16_split(v, hi, lo);
    g_wh[i] = hi;
    g_wl[i] = lo;
}

// ---------------- GEMM: mma.sync, 3-stage cp.async, optional in-smem BN transform
// of B tiles (TRF: B holds raw t; apply na*t+nb, relu, re-split before MMA),
// epilogue: stats always; output either fp32 [c][n] g_t or raw bf16 pair [n][c].
template <int K, int RSX, bool TRF, bool EPIBT>
__global__ void __launch_bounds__(256, 2) gemm_mma_kernel(
    const __nv_bfloat16* __restrict__ Wh, const __nv_bfloat16* __restrict__ Wl,
    const __nv_bfloat16* __restrict__ Bh, const __nv_bfloat16* __restrict__ Bl,
    const float* __restrict__ bias,
    const float* __restrict__ naL, const float* __restrict__ nbL,
    __nv_bfloat16* __restrict__ Dh, __nv_bfloat16* __restrict__ Dl) {
    extern __shared__ __nv_bfloat16 sm[];
    const int ASZ = BM * SST;
    const int BSZ = BN * SST;
    const uint32_t ASZB = ASZ * 2, BSZB = BSZ * 2;
    const uint32_t STGB = 2 * ASZB + 2 * BSZB;

    int tid = threadIdx.x, lane = tid & 31, wid = tid >> 5;
    int wm = wid & 3, wn = wid >> 2;
    int b = blockIdx.z;
    int n0 = blockIdx.x * BN, m0 = blockIdx.y * BM;
    int r = lane >> 2, qk = lane & 3;

    uint32_t sbase = smem_u32(sm);

    int g8 = lane >> 3, lr = lane & 7;
    uint32_t aoff[2], boff[2];
#pragma unroll
    for (int i = 0; i < 2; i++)
        aoff[i] = ((wm * 32 + i * 16 + (g8 & 1) * 8 + lr) * SST + (g8 >> 1) * 8) * 2;
#pragma unroll
    for (int p = 0; p < 2; p++)
        boff[p] = ((wn * 32 + p * 16 + (g8 >> 1) * 8 + lr) * SST + (g8 & 1) * 8) * 2;

    const __nv_bfloat16* bth_b = Bh + (size_t)b * NP * RSX;
    const __nv_bfloat16* btl_b = Bl + (size_t)b * NP * RSX;
    int brow = tid >> 2, bc = tid & 3;

    float acc[2][4][4];
#pragma unroll
    for (int i = 0; i < 2; i++)
#pragma unroll
        for (int j = 0; j < 4; j++)
#pragma unroll
            for (int q = 0; q < 4; q++) acc[i][j][q] = 0.f;

    const int NT = K / BKc;

    auto issue = [&](int t) {
        int kc = t * BKc;
        uint32_t st = sbase + (uint32_t)(t % 3) * STGB;
#pragma unroll
        for (int i = 0; i < 2; i++) {
            int idx = tid + i * 256;
            int row = idx >> 2, c = idx & 3;
            uint32_t d = st + (uint32_t)(row * SST + c * 8) * 2;
            cp16(d, Wh + (size_t)(m0 + row) * K + kc + c * 8);
            cp16(d + ASZB, Wl + (size_t)(m0 + row) * K + kc + c * 8);
        }
        {
            uint32_t d = st + 2 * ASZB + (uint32_t)(brow * SST + bc * 8) * 2;
            cp16(d, bth_b + (size_t)(n0 + brow) * RSX + kc + bc * 8);
            cp16(d + BSZB, btl_b + (size_t)(n0 + brow) * RSX + kc + bc * 8);
        }
        asm volatile("cp.async.commit_group;" ::: "memory");
    };

    issue(0);
    if (NT > 1) issue(1);

    for (int t = 0; t < NT; t++) {
        if (t + 1 < NT) {
            asm volatile("cp.async.wait_group 1;" ::: "memory");
        } else {
            asm volatile("cp.async.wait_group 0;" ::: "memory");
        }
        __syncthreads();
        uint32_t st = sbase + (uint32_t)(t % 3) * STGB;

        if (TRF) {
            // BN+relu transform of the raw-t B tile, in place (64 rows x 32 k)
            int kc = t * BKc;
            int row = tid >> 2, k0 = (tid & 3) * 8;
            char* stc = (char*)sm + (size_t)(t % 3) * STGB;
            __nv_bfloat16* bhp = (__nv_bfloat16*)(stc + 2 * ASZB) + row * SST + k0;
            __nv_bfloat16* blp = (__nv_bfloat16*)(stc + 2 * ASZB + BSZB) + row * SST + k0;
            uint4 uh = *(uint4*)bhp;
            uint4 ul = *(uint4*)blp;
            __nv_bfloat16* hv = (__nv_bfloat16*)&uh;
            __nv_bfloat16* lv = (__nv_bfloat16*)&ul;
#pragma unroll
            for (int i = 0; i < 8; i++) {
                float v = __bfloat162float(hv[i]) + __bfloat162float(lv[i]);
                float u = fmaxf(fmaf(naL[kc + k0 + i], v, nbL[kc + k0 + i]), 0.f);
                bf16_split(u, hv[i], lv[i]);
            }
            *(uint4*)bhp = uh;
            *(uint4*)blp = ul;
            __syncthreads();
        }

#pragma unroll
        for (int k16 = 0; k16 < BKc; k16 += 16) {
            uint32_t kb = (uint32_t)k16 * 2;
            uint32_t ah[2][4], al[2][4], bh[2][4], bl[2][4];
            ldsm4(ah[0], st + aoff[0] + kb);
            ldsm4(ah[1], st + aoff[1] + kb);
            ldsm4(al[0], st + ASZB + aoff[0] + kb);
            ldsm4(al[1], st + ASZB + aoff[1] + kb);
            ldsm4(bh[0], st + 2 * ASZB + boff[0] + kb);
            ldsm4(bh[1], st + 2 * ASZB + boff[1] + kb);
            ldsm4(bl[0], st + 2 * ASZB + BSZB + boff[0] + kb);
            ldsm4(bl[1], st + 2 * ASZB + BSZB + boff[1] + kb);
#pragma unroll
            for (int i = 0; i < 2; i++)
#pragma unroll
                for (int j = 0; j < 4; j++) {
                    const uint32_t* bhj = &bh[j >> 1][(j & 1) * 2];
                    const uint32_t* blj = &bl[j >> 1][(j & 1) * 2];
                    mma16816(acc[i][j], ah[i], bhj);
                    mma16816(acc[i][j], ah[i], blj);
                    mma16816(acc[i][j], al[i], bhj);
                }
        }
        if (t + 2 < NT) issue(t + 2);
    }

    // ---- epilogue ----
    // bias add into acc
#pragma unroll
    for (int i = 0; i < 2; i++) {
        int m = m0 + wm * 32 + i * 16 + r;
        float bs0 = bias[m], bs8 = bias[m + 8];
#pragma unroll
        for (int j = 0; j < 4; j++) {
            acc[i][j][0] += bs0; acc[i][j][1] += bs0;
            acc[i][j][2] += bs8; acc[i][j][3] += bs8;
        }
    }

    if (!EPIBT) {
        float* Yb = g_t + (size_t)b * COUT * NP;
#pragma unroll
        for (int i = 0; i < 2; i++) {
            int m = m0 + wm * 32 + i * 16 + r;
#pragma unroll
            for (int j = 0; j < 4; j++) {
                int n = n0 + wn * 32 + j * 8 + qk * 2;
                *(float2*)(Yb + (size_t)m * NP + n)       = make_float2(acc[i][j][0], acc[i][j][1]);
                *(float2*)(Yb + (size_t)(m + 8) * NP + n) = make_float2(acc[i][j][2], acc[i][j][3]);
            }
        }
    }

    // stats
    float ssum[4] = {0.f, 0.f, 0.f, 0.f}, ssq[4] = {0.f, 0.f, 0.f, 0.f};
#pragma unroll
    for (int i = 0; i < 2; i++)
#pragma unroll
        for (int j = 0; j < 4; j++) {
            float v0 = acc[i][j][0], v1 = acc[i][j][1], v2 = acc[i][j][2], v3 = acc[i][j][3];
            ssum[i * 2]     += v0 + v1;  ssq[i * 2]     += v0 * v0 + v1 * v1;
            ssum[i * 2 + 1] += v2 + v3;  ssq[i * 2 + 1] += v2 * v2 + v3 * v3;
        }
#pragma unroll
    for (int o = 1; o < 4; o <<= 1) {
#pragma unroll
        for (int k = 0; k < 4; k++) {
            ssum[k] += __shfl_xor_sync(0xffffffff, ssum[k], o);
            ssq[k]  += __shfl_xor_sync(0xffffffff, ssq[k], o);
        }
    }
    float* sb = (float*)sm;
    __syncthreads();
    if (qk == 0) {
#pragma unroll
        for (int k = 0; k < 4; k++) {
            int row = wm * 32 + (k >> 1) * 16 + (k & 1) * 8 + r;
            sb[(wn * 128 + row) * 2]     = ssum[k];
            sb[(wn * 128 + row) * 2 + 1] = ssq[k];
        }
    }
    __syncthreads();
    if (tid < 128) {
        float S = sb[tid * 2]     + sb[(128 + tid) * 2];
        float Q = sb[tid * 2 + 1] + sb[(128 + tid) * 2 + 1];
        int slot = blockIdx.x + gridDim.x * blockIdx.z;
        g_psum[(size_t)(m0 + tid) * NSLOT + slot] = S;
        g_psq [(size_t)(m0 + tid) * NSLOT + slot] = Q;
    }

    if (EPIBT) {
        // stage to smem [n][m] (stride 133), then write raw t as bf16 pair [n][c]
        __syncthreads();
        float* ts2 = (float*)sm;
#pragma unroll
        for (int i = 0; i < 2; i++) {
            int ml = wm * 32 + i * 16 + r;
#pragma unroll
            for (int j = 0; j < 4; j++) {
                int nl = wn * 32 + j * 8 + qk * 2;
                ts2[nl * 133 + ml]           = acc[i][j][0];
                ts2[(nl + 1) * 133 + ml]     = acc[i][j][1];
                ts2[nl * 133 + ml + 8]       = acc[i][j][2];
                ts2[(nl + 1) * 133 + ml + 8] = acc[i][j][3];
            }
        }
        __syncthreads();
        int nl = tid & 63, mch = (tid >> 6) * 32;
        uint32_t hiw[16], low[16];
#pragma unroll
        for (int q = 0; q < 16; q++) {
            float f0 = ts2[nl * 133 + mch + 2 * q];
            float f1 = ts2[nl * 133 + mch + 2 * q + 1];
            __nv_bfloat16 h0, l0, h1, l1;
            bf16_split(f0, h0, l0);
            bf16_split(f1, h1, l1);
            __nv_bfloat162 hh; hh.x = h0; hh.y = h1;
            __nv_bfloat162 ll; ll.x = l0; ll.y = l1;
            hiw[q] = *(uint32_t*)&hh;
            low[q] = *(uint32_t*)&ll;
        }
        size_t off = ((size_t)b * NP + n0 + nl) * RSB + m0 + mch;
#pragma unroll
        for (int p = 0; p < 4; p++) {
            uint4 uh, ul;
            uh.x = hiw[4 * p]; uh.y = hiw[4 * p + 1]; uh.z = hiw[4 * p + 2]; uh.w = hiw[4 * p + 3];
            ul.x = low[4 * p]; ul.y = low[4 * p + 1]; ul.z = low[4 * p + 2]; ul.w = low[4 * p + 3];
            *(uint4*)(Dh + off + p * 8) = uh;
            *(uint4*)(Dl + off + p * 8) = ul;
        }
    }
}

// ---------------- finalize BN into slot ----------------
__global__ void __launch_bounds__(256) finalize_kernel(const float* __restrict__ gamma,
                                                       const float* __restrict__ beta,
                                                       int slot) {
    int c = blockIdx.x, tid = threadIdx.x;
    float s = g_psum[(size_t)c * NSLOT + tid] + g_psum[(size_t)c * NSLOT + 256 + tid];
    float q = g_psq [(size_t)c * NSLOT + tid] + g_psq [(size_t)c * NSLOT + 256 + tid];
    __shared__ float rs[256], rq[256];
    rs[tid] = s; rq[tid] = q;
    __syncthreads();
    for (int o = 128; o > 0; o >>= 1) {
        if (tid < o) { rs[tid] += rs[tid + o]; rq[tid] += rq[tid + o]; }
        __syncthreads();
    }
    if (tid == 0) {
        float inv = 1.0f / (float)(BB * NP);
        float mean = rs[0] * inv;
        float var = rq[0] * inv - mean * mean;
        float a = gamma[c] * rsqrtf(var + BN_EPS);
        g_na[slot * COUT + c] = a;
        g_nb[slot * COUT + c] = beta[c] - mean * a;
    }
}

// ---------------- apply_x1: trunk = relu(bn2(t2_f32) + relu(bn0(tfuse_pair))) ----
__global__ void apply_x1_kernel() {
    __shared__ float ts[32][33];
    const float* na2 = g_na + 2 * COUT; const float* nb2 = g_nb + 2 * COUT;
    const float* na0 = g_na;            const float* nb0 = g_nb;
    int b = blockIdx.z;
    int n0 = blockIdx.x * 32, c0 = blockIdx.y * 32;
    int tx = threadIdx.x, ty = threadIdx.y;
#pragma unroll
    for (int j = 0; j < 32; j += 8) {
        int c = c0 + ty + j;
        size_t off = ((size_t)b * COUT + c) * NP + n0 + tx;
        ts[ty + j][tx] = fmaf(na2[c], g_t[off], nb2[c]);
    }
    __syncthreads();
#pragma unroll
    for (int j = 0; j < 32; j += 8) {
        int n = n0 + ty + j, c = c0 + tx;
        size_t o = ((size_t)b * NP + n) * RSB + c;
        float tf = __bfloat162float(g_tfh[o]) + __bfloat162float(g_tfl[o]);
        float x0 = fmaxf(fmaf(na0[c], tf, nb0[c]), 0.f);
        float v = fmaxf(ts[tx][ty + j] + x0, 0.f);
        __nv_bfloat16 hi, lo;
        bf16_split(v, hi, lo);
        g_bth[o] = hi;
        g_btl[o] = lo;
    }
}

// ---------------- apply_final: out[c][n] = relu(bn4(t2) + trunk) ----------------
__global__ void apply_final_kernel(float* __restrict__ O) {
    __shared__ float ts[32][33];
    __shared__ float t2[32][33];
    const float* na4 = g_na + 4 * COUT; const float* nb4 = g_nb + 4 * COUT;
    int b = blockIdx.z;
    int n0 = blockIdx.x * 32, c0 = blockIdx.y * 32;
    int tx = threadIdx.x, ty = threadIdx.y;
#pragma unroll
    for (int j = 0; j < 32; j += 8) {
        int c = c0 + ty + j;
        size_t off = ((size_t)b * COUT + c) * NP + n0 + tx;
        ts[ty + j][tx] = fmaf(na4[c], g_t[off], nb4[c]);
    }
    __syncthreads();
#pragma unroll
    for (int j = 0; j < 32; j += 8) {
        int n = n0 + ty + j, c = c0 + tx;
        size_t o = ((size_t)b * NP + n) * RSB + c;
        float res = __bfloat162float(g_bth[o]) + __bfloat162float(g_btl[o]);
        t2[tx][ty + j] = fmaxf(ts[tx][ty + j] + res, 0.f);
    }
    __syncthreads();
#pragma unroll
    for (int j = 0; j < 32; j += 8)
        O[((size_t)b * COUT + c0 + ty + j) * NP + n0 + tx] = t2[ty + j][tx];
}

// ---------------- launch ----------------
extern "C" void kernel_launch(void* const* d_in, const int* in_sizes, int n_in,
                              void* d_out, int out_size) {
    const float* xyz1    = (const float*)d_in[0];
    const float* xyz2    = (const float*)d_in[1];
    const float* points1 = (const float*)d_in[2];
    const float* points2 = (const float*)d_in[3];
    const float* fuse_W  = (const float*)d_in[4];
    const float* fuse_b  = (const float*)d_in[5];
    const float* fuse_g  = (const float*)d_in[6];
    const float* fuse_be = (const float*)d_in[7];
    const float* blk_W1  = (const float*)d_in[8];
    const float* blk_b1  = (const float*)d_in[9];
    const float* blk_g1  = (const float*)d_in[10];
    const float* blk_be1 = (const float*)d_in[11];
    const float* blk_W2  = (const float*)d_in[12];
    const float* blk_b2  = (const float*)d_in[13];
    const float* blk_g2  = (const float*)d_in[14];
    const float* blk_be2 = (const float*)d_in[15];
    float* out = (float*)d_out;

    void* pv;
    cudaGetSymbolAddress(&pv, g_wh);  __nv_bfloat16* wh = (__nv_bfloat16*)pv;
    cudaGetSymbolAddress(&pv, g_wl);  __nv_bfloat16* wl = (__nv_bfloat16*)pv;
    cudaGetSymbolAddress(&pv, g_bth); __nv_bfloat16* th = (__nv_bfloat16*)pv;
    cudaGetSymbolAddress(&pv, g_btl); __nv_bfloat16* tl = (__nv_bfloat16*)pv;
    cudaGetSymbolAddress(&pv, g_tfh); __nv_bfloat16* tfh = (__nv_bfloat16*)pv;
    cudaGetSymbolAddress(&pv, g_tfl); __nv_bfloat16* tfl = (__nv_bfloat16*)pv;
    cudaGetSymbolAddress(&pv, g_byh); __nv_bfloat16* yh = (__nv_bfloat16*)pv;
    cudaGetSymbolAddress(&pv, g_byl); __nv_bfloat16* yl = (__nv_bfloat16*)pv;
    cudaGetSymbolAddress(&pv, g_na);  float* na = (float*)pv;
    cudaGetSymbolAddress(&pv, g_nb);  float* nb = (float*)pv;

    const int SMEM_GEMM = 3 * (2 * BM * SST + 2 * BN * SST) * 2;  // 92160 B
    cudaFuncSetAttribute(gemm_mma_kernel<CIN, RSI, false, true>, cudaFuncAttributeMaxDynamicSharedMemorySize, SMEM_GEMM);
    cudaFuncSetAttribute(gemm_mma_kernel<COUT, RSB, true,  true>, cudaFuncAttributeMaxDynamicSharedMemorySize, SMEM_GEMM);
    cudaFuncSetAttribute(gemm_mma_kernel<COUT, RSB, false, true>, cudaFuncAttributeMaxDynamicSharedMemorySize, SMEM_GEMM);
    cudaFuncSetAttribute(gemm_mma_kernel<COUT, RSB, true,  false>, cudaFuncAttributeMaxDynamicSharedMemorySize, SMEM_GEMM);

    dim3 ggrid(NP / BN, COUT / BM, BB);
    dim3 agrid(NP / 32, COUT / 32, BB);
    dim3 ablk(32, 8);

    convert_w_all_kernel<<<(WTOT + 255) / 256, 256>>>(fuse_W, blk_W1, blk_W2);
    transpose_p2_kernel<<<dim3(SP / 32, D2 / 32, BB), ablk>>>(points2);
    knn_kernel<<<dim3(NP / 128, BB), 128>>>(xyz1, xyz2);
    interp_kernel<<<dim3(NP / 32, BB), 256>>>();
    convert_p1_kernel<<<dim3(NP / 32, D1 / 32, BB), ablk>>>(points1);

    // fuse: B = input concat; writes raw t_fuse pair
    gemm_mma_kernel<CIN, RSI, false, true><<<ggrid, 256, SMEM_GEMM>>>(
        wh, wl, th, tl, fuse_b, nullptr, nullptr, tfh, tfl);
    finalize_kernel<<<COUT, 256>>>(fuse_g, fuse_be, 0);

    // blk1_0: B = raw t_fuse + transform(slot0); writes raw t1 pair
    gemm_mma_kernel<COUT, RSB, true, true><<<ggrid, 256, SMEM_GEMM>>>(
        wh + OFF_W1, wl + OFF_W1, tfh, tfl, blk_b1, na, nb, yh, yl);
    finalize_kernel<<<COUT, 256>>>(blk_g1, blk_be1, 1);

    // blk2_0: B = raw t1 + transform(slot1); writes fp32 g_t
    gemm_mma_kernel<COUT, RSB, true, false><<<ggrid, 256, SMEM_GEMM>>>(
        wh + OFF_W2, wl + OFF_W2, yh, yl, blk_b2, na + COUT, nb + COUT, nullptr, nullptr);
    finalize_kernel<<<COUT, 256>>>(blk_g2, blk_be2, 2);

    // x1 = relu(bn2(t2) + relu(bn0(t_fuse))) -> trunk pair (stride 256)
    apply_x1_kernel<<<agrid, ablk>>>();

    // blk1_1: B = trunk (already activated); writes raw t1 pair
    gemm_mma_kernel<COUT, RSB, false, true><<<ggrid, 256, SMEM_GEMM>>>(
        wh + OFF_W1 + CC, wl + OFF_W1 + CC, th, tl, blk_b1 + COUT, nullptr, nullptr, yh, yl);
    finalize_kernel<<<COUT, 256>>>(blk_g1 + COUT, blk_be1 + COUT, 3);

    // blk2_1: B = raw t1 + transform(slot3); writes fp32 g_t
    gemm_mma_kernel<COUT, RSB, true, false><<<ggrid, 256, SMEM_GEMM>>>(
        wh + OFF_W2 + CC, wl + OFF_W2 + CC, yh, yl, blk_b2 + COUT,
        na + 3 * COUT, nb + 3 * COUT, nullptr, nullptr);
    finalize_kernel<<<COUT, 256>>>(blk_g2 + COUT, blk_be2 + COUT, 4);

    // out = relu(bn4(t2) + trunk)
    apply_final_kernel<<<agrid, ablk>>>(out);
}

// round 8
// speedup vs baseline: 1.1658x; 1.1658x over previous
#include <cuda_runtime.h>
#include <cuda_bf16.h>
#include <cstdint>

#define BB   4
#define NP   8192
#define SP   2048
#define D1   128
#define D2   256
#define CIN  384
#define COUT 256
#define RS   384          // row stride (K elems) of transposed bf16 activation buffers
#define BN_EPS 1e-5f

#define BM   128
#define BN   64
#define BKc  32
#define SST  40           // smem row stride in bf16 (80 B, conflict-free for ldmatrix)
#define NSLOT 512

#define WTOT   (COUT * CIN + 4 * COUT * COUT)
#define OFF_W1 (COUT * CIN)
#define OFF_W2 (OFF_W1 + 2 * COUT * COUT)
#define CC     (COUT * COUT)

// ---------------- scratch ----------------
__device__ float g_p2t[BB * SP * D2];
__device__ float g_t  [(size_t)BB * COUT * NP];          // fp32 raw GEMM out
__device__ __nv_bfloat16 g_bth[(size_t)BB * NP * RS];    // trunk / input concat [n][c] hi
__device__ __nv_bfloat16 g_btl[(size_t)BB * NP * RS];    // lo
__device__ __nv_bfloat16 g_byh[(size_t)BB * NP * RS];    // block intermediate y hi
__device__ __nv_bfloat16 g_byl[(size_t)BB * NP * RS];
__device__ __nv_bfloat16 g_wh[WTOT];
__device__ __nv_bfloat16 g_wl[WTOT];
__device__ float g_psum[COUT * NSLOT];
__device__ float g_psq [COUT * NSLOT];
__device__ int   g_idx[BB * NP * 3];
__device__ float g_w  [BB * NP * 3];
__device__ float g_na [COUT];
__device__ float g_nb [COUT];

__device__ __forceinline__ void bf16_split(float v, __nv_bfloat16& hi, __nv_bfloat16& lo) {
    hi = __float2bfloat16(v);
    lo = __float2bfloat16(v - __bfloat162float(hi));
}
__device__ __forceinline__ uint32_t smem_u32(const void* p) {
    uint32_t a;
    asm("{ .reg .u64 t; cvta.to.shared.u64 t, %1; cvt.u32.u64 %0, t; }" : "=r"(a) : "l"(p));
    return a;
}
__device__ __forceinline__ void mma16816(float* c, const uint32_t* a, const uint32_t* b) {
    asm volatile(
        "mma.sync.aligned.m16n8k16.row.col.f32.bf16.bf16.f32 "
        "{%0,%1,%2,%3}, {%4,%5,%6,%7}, {%8,%9}, {%0,%1,%2,%3};"
        : "+f"(c[0]), "+f"(c[1]), "+f"(c[2]), "+f"(c[3])
        : "r"(a[0]), "r"(a[1]), "r"(a[2]), "r"(a[3]), "r"(b[0]), "r"(b[1]));
}
__device__ __forceinline__ void ldsm4(uint32_t* r, uint32_t addr) {
    asm volatile("ldmatrix.sync.aligned.m8n8.x4.shared.b16 {%0,%1,%2,%3}, [%4];"
        : "=r"(r[0]), "=r"(r[1]), "=r"(r[2]), "=r"(r[3]) : "r"(addr));
}
__device__ __forceinline__ void cp16(uint32_t daddr, const void* src) {
    asm volatile("cp.async.cg.shared.global [%0], [%1], 16;" :: "r"(daddr), "l"(src));
}

// ---------------- KNN ----------------
__global__ void __launch_bounds__(128) knn_kernel(const float* __restrict__ xyz1,
                                                  const float* __restrict__ xyz2) {
    __shared__ float sx[SP], sy[SP], sz[SP], sn[SP];
    int b = blockIdx.y;
    const float* x2 = xyz2 + (size_t)b * 3 * SP;
    for (int i = threadIdx.x; i < SP; i += 128) {
        float X = x2[i], Y = x2[SP + i], Z = x2[2 * SP + i];
        sx[i] = X; sy[i] = Y; sz[i] = Z; sn[i] = X * X + Y * Y + Z * Z;
    }
    __syncthreads();
    int n = blockIdx.x * 128 + threadIdx.x;
    const float* x1 = xyz1 + (size_t)b * 3 * NP;
    float qx = x1[n], qy = x1[NP + n], qz = x1[2 * NP + n];
    float qn = qx * qx + qy * qy + qz * qz;

    float d0 = 3.4e38f, d1 = 3.4e38f, d2v = 3.4e38f;
    int i0 = 0, i1 = 0, i2 = 0;
#pragma unroll 4
    for (int s = 0; s < SP; s++) {
        float dot = qx * sx[s] + qy * sy[s] + qz * sz[s];
        float d = qn + sn[s] - 2.0f * dot;
        if (d < d2v) {
            if (d < d1) {
                d2v = d1; i2 = i1;
                if (d < d0) { d1 = d0; i1 = i0; d0 = d; i0 = s; }
                else        { d1 = d;  i1 = s; }
            } else { d2v = d; i2 = s; }
        }
    }
    float r0 = 1.0f / (d0 + 1e-8f);
    float r1 = 1.0f / (d1 + 1e-8f);
    float r2 = 1.0f / (d2v + 1e-8f);
    float inv = 1.0f / (r0 + r1 + r2);
    size_t base = ((size_t)b * NP + n) * 3;
    g_idx[base] = i0; g_idx[base + 1] = i1; g_idx[base + 2] = i2;
    g_w[base] = r0 * inv; g_w[base + 1] = r1 * inv; g_w[base + 2] = r2 * inv;
}

// ---------------- transpose points2 [b][c][s] -> [b][s][c] ----------------
__global__ void transpose_p2_kernel(const float* __restrict__ p2) {
    __shared__ float tile[32][33];
    int b = blockIdx.z;
    int s0 = blockIdx.x * 32, c0 = blockIdx.y * 32;
    int tx = threadIdx.x, ty = threadIdx.y;
#pragma unroll
    for (int j = 0; j < 32; j += 8)
        tile[ty + j][tx] = p2[((size_t)b * D2 + c0 + ty + j) * SP + s0 + tx];
    __syncthreads();
    float* dst = g_p2t + (size_t)b * SP * D2;
#pragma unroll
    for (int j = 0; j < 32; j += 8)
        dst[(size_t)(s0 + ty + j) * D2 + c0 + tx] = tile[tx][ty + j];
}

// ---------------- interp: concat rows [n][128..383], bf16x2 stores ----------------
__global__ void __launch_bounds__(256) interp_kernel() {
    __shared__ float sw[32][3];
    __shared__ int   si[32][3];
    int b = blockIdx.y;
    int n0 = blockIdx.x * 32;
    int tid = threadIdx.x;
    if (tid < 96) {
        int q = tid / 3, k = tid % 3;
        size_t base = ((size_t)b * NP + n0 + q) * 3 + k;
        sw[q][k] = g_w[base];
        si[q][k] = g_idx[base];
    }
    __syncthreads();
    const float* f2 = g_p2t + (size_t)b * SP * D2;
    int c = (tid & 127) * 2;       // pair of channels
    int half = tid >> 7;           // 0..1
#pragma unroll 4
    for (int qq = 0; qq < 16; qq++) {
        int q = half * 16 + qq;
        float w0 = sw[q][0], w1 = sw[q][1], w2 = sw[q][2];
        float2 a0 = *(const float2*)(f2 + (size_t)si[q][0] * D2 + c);
        float2 a1 = *(const float2*)(f2 + (size_t)si[q][1] * D2 + c);
        float2 a2 = *(const float2*)(f2 + (size_t)si[q][2] * D2 + c);
        float vx = w0 * a0.x + w1 * a1.x + w2 * a2.x;
        float vy = w0 * a0.y + w1 * a1.y + w2 * a2.y;
        __nv_bfloat16 hx, lx, hy, ly;
        bf16_split(vx, hx, lx);
        bf16_split(vy, hy, ly);
        __nv_bfloat162 hh; hh.x = hx; hh.y = hy;
        __nv_bfloat162 ll; ll.x = lx; ll.y = ly;
        size_t o = ((size_t)b * NP + n0 + q) * RS + D1 + c;
        *(__nv_bfloat162*)(g_bth + o) = hh;
        *(__nv_bfloat162*)(g_btl + o) = ll;
    }
}

// ---------------- points1 -> concat rows [n][0..127], 8B stores ----------------
__global__ void convert_p1_kernel(const float* __restrict__ p1) {
    __shared__ float tile[32][33];
    int b = blockIdx.z;
    int n0 = blockIdx.x * 32, c0 = blockIdx.y * 32;
    int tx = threadIdx.x, ty = threadIdx.y;
#pragma unroll
    for (int j = 0; j < 32; j += 8)
        tile[ty + j][tx] = p1[((size_t)b * D1 + c0 + ty + j) * NP + n0 + tx];
    __syncthreads();
    int u = ty * 32 + tx;
    int n_l = u >> 3, cg = u & 7;      // 4 channels per thread
    uint32_t hw[2], lw[2];
#pragma unroll
    for (int p = 0; p < 2; p++) {
        float v0 = tile[cg * 4 + 2 * p][n_l];
        float v1 = tile[cg * 4 + 2 * p + 1][n_l];
        __nv_bfloat16 h0, l0, h1, l1;
        bf16_split(v0, h0, l0);
        bf16_split(v1, h1, l1);
        __nv_bfloat162 hh; hh.x = h0; hh.y = h1;
        __nv_bfloat162 ll; ll.x = l0; ll.y = l1;
        hw[p] = *(uint32_t*)&hh;
        lw[p] = *(uint32_t*)&ll;
    }
    size_t o = ((size_t)b * NP + n0 + n_l) * RS + c0 + cg * 4;
    *(uint2*)(g_bth + o) = make_uint2(hw[0], hw[1]);
    *(uint2*)(g_btl + o) = make_uint2(lw[0], lw[1]);
}

// ---------------- all weights fp32 -> bf16 hi/lo ----------------
__global__ void convert_w_all_kernel(const float* __restrict__ fw,
                                     const float* __restrict__ w1,
                                     const float* __restrict__ w2) {
    int i = blockIdx.x * 256 + threadIdx.x;
    if (i >= WTOT) return;
    float v;
    if (i < OFF_W1)      v = fw[i];
    else if (i < OFF_W2) v = w1[i - OFF_W1];
    else                 v = w2[i - OFF_W2];
    __nv_bfloat16 hi, lo;
    bf16_split(v, hi, lo);
    g_wh[i] = hi;
    g_wl[i] = lo;
}

// ---------------- GEMM (exact R6): mma.sync, 3-stage cp.async, 1 sync/K-tile,
// fused partial BN stats. t[b][m][n] = sum_c W[m][c]*X[b][c][n] + bias[m].
template <int K>
__global__ void __launch_bounds__(256) gemm_mma_kernel(
    const __nv_bfloat16* __restrict__ Wh, const __nv_bfloat16* __restrict__ Wl,
    const __nv_bfloat16* __restrict__ Bth, const __nv_bfloat16* __restrict__ Btl,
    const float* __restrict__ bias) {
    extern __shared__ __nv_bfloat16 sm[];
    const int ASZ = BM * SST;
    const int BSZ = BN * SST;
    const uint32_t ASZB = ASZ * 2, BSZB = BSZ * 2;
    const uint32_t STGB = 2 * ASZB + 2 * BSZB;

    int tid = threadIdx.x, lane = tid & 31, wid = tid >> 5;
    int wm = wid & 3, wn = wid >> 2;
    int b = blockIdx.z;
    int n0 = blockIdx.x * BN, m0 = blockIdx.y * BM;
    int r = lane >> 2, qk = lane & 3;

    uint32_t sbase = smem_u32(sm);

    int g8 = lane >> 3, lr = lane & 7;
    uint32_t aoff[2], boff[2];
#pragma unroll
    for (int i = 0; i < 2; i++)
        aoff[i] = ((wm * 32 + i * 16 + (g8 & 1) * 8 + lr) * SST + (g8 >> 1) * 8) * 2;
#pragma unroll
    for (int p = 0; p < 2; p++)
        boff[p] = ((wn * 32 + p * 16 + (g8 >> 1) * 8 + lr) * SST + (g8 & 1) * 8) * 2;

    const __nv_bfloat16* bth_b = Bth + (size_t)b * NP * RS;
    const __nv_bfloat16* btl_b = Btl + (size_t)b * NP * RS;
    int brow = tid >> 2, bc = tid & 3;

    float acc[2][4][4];
#pragma unroll
    for (int i = 0; i < 2; i++)
#pragma unroll
        for (int j = 0; j < 4; j++)
#pragma unroll
            for (int q = 0; q < 4; q++) acc[i][j][q] = 0.f;

    const int NT = K / BKc;

    auto issue = [&](int t) {
        int kc = t * BKc;
        uint32_t st = sbase + (uint32_t)(t % 3) * STGB;
#pragma unroll
        for (int i = 0; i < 2; i++) {
            int idx = tid + i * 256;
            int row = idx >> 2, c = idx & 3;
            uint32_t d = st + (uint32_t)(row * SST + c * 8) * 2;
            cp16(d, Wh + (size_t)(m0 + row) * K + kc + c * 8);
            cp16(d + ASZB, Wl + (size_t)(m0 + row) * K + kc + c * 8);
        }
        {
            uint32_t d = st + 2 * ASZB + (uint32_t)(brow * SST + bc * 8) * 2;
            cp16(d, bth_b + (size_t)(n0 + brow) * RS + kc + bc * 8);
            cp16(d + BSZB, btl_b + (size_t)(n0 + brow) * RS + kc + bc * 8);
        }
        asm volatile("cp.async.commit_group;" ::: "memory");
    };

    issue(0);
    if (NT > 1) issue(1);

    for (int t = 0; t < NT; t++) {
        if (t + 1 < NT) {
            asm volatile("cp.async.wait_group 1;" ::: "memory");
        } else {
            asm volatile("cp.async.wait_group 0;" ::: "memory");
        }
        __syncthreads();
        uint32_t st = sbase + (uint32_t)(t % 3) * STGB;
#pragma unroll
        for (int k16 = 0; k16 < BKc; k16 += 16) {
            uint32_t kb = (uint32_t)k16 * 2;
            uint32_t ah[2][4], al[2][4], bh[2][4], bl[2][4];
            ldsm4(ah[0], st + aoff[0] + kb);
            ldsm4(ah[1], st + aoff[1] + kb);
            ldsm4(al[0], st + ASZB + aoff[0] + kb);
            ldsm4(al[1], st + ASZB + aoff[1] + kb);
            ldsm4(bh[0], st + 2 * ASZB + boff[0] + kb);
            ldsm4(bh[1], st + 2 * ASZB + boff[1] + kb);
            ldsm4(bl[0], st + 2 * ASZB + BSZB + boff[0] + kb);
            ldsm4(bl[1], st + 2 * ASZB + BSZB + boff[1] + kb);
#pragma unroll
            for (int i = 0; i < 2; i++)
#pragma unroll
                for (int j = 0; j < 4; j++) {
                    const uint32_t* bhj = &bh[j >> 1][(j & 1) * 2];
                    const uint32_t* blj = &bl[j >> 1][(j & 1) * 2];
                    mma16816(acc[i][j], ah[i], bhj);
                    mma16816(acc[i][j], ah[i], blj);
                    mma16816(acc[i][j], al[i], bhj);
                }
        }
        if (t + 2 < NT) issue(t + 2);
    }

    // ---- epilogue: bias add, store fp32 t, partial stats ----
    float* Yb = g_t + (size_t)b * COUT * NP;
    float ssum[4] = {0.f, 0.f, 0.f, 0.f}, ssq[4] = {0.f, 0.f, 0.f, 0.f};
#pragma unroll
    for (int i = 0; i < 2; i++) {
        int m = m0 + wm * 32 + i * 16 + r;
        float bs0 = bias[m], bs8 = bias[m + 8];
#pragma unroll
        for (int j = 0; j < 4; j++) {
            int n = n0 + wn * 32 + j * 8 + qk * 2;
            float v0 = acc[i][j][0] + bs0, v1 = acc[i][j][1] + bs0;
            float v2 = acc[i][j][2] + bs8, v3 = acc[i][j][3] + bs8;
            *(float2*)(Yb + (size_t)m * NP + n)       = make_float2(v0, v1);
            *(float2*)(Yb + (size_t)(m + 8) * NP + n) = make_float2(v2, v3);
            ssum[i * 2]     += v0 + v1;  ssq[i * 2]     += v0 * v0 + v1 * v1;
            ssum[i * 2 + 1] += v2 + v3;  ssq[i * 2 + 1] += v2 * v2 + v3 * v3;
        }
    }
#pragma unroll
    for (int o = 1; o < 4; o <<= 1) {
#pragma unroll
        for (int k = 0; k < 4; k++) {
            ssum[k] += __shfl_xor_sync(0xffffffff, ssum[k], o);
            ssq[k]  += __shfl_xor_sync(0xffffffff, ssq[k], o);
        }
    }
    float* sb = (float*)sm;
    __syncthreads();
    if (qk == 0) {
#pragma unroll
        for (int k = 0; k < 4; k++) {
            int row = wm * 32 + (k >> 1) * 16 + (k & 1) * 8 + r;
            sb[(wn * 128 + row) * 2]     = ssum[k];
            sb[(wn * 128 + row) * 2 + 1] = ssq[k];
        }
    }
    __syncthreads();
    if (tid < 128) {
        float S = sb[tid * 2]     + sb[(128 + tid) * 2];
        float Q = sb[tid * 2 + 1] + sb[(128 + tid) * 2 + 1];
        int slot = blockIdx.x + gridDim.x * blockIdx.z;
        g_psum[(size_t)(m0 + tid) * NSLOT + slot] = S;
        g_psq [(size_t)(m0 + tid) * NSLOT + slot] = Q;
    }
}

// ---------------- finalize BN ----------------
__global__ void __launch_bounds__(256) finalize_kernel(const float* __restrict__ gamma,
                                                       const float* __restrict__ beta) {
    int c = blockIdx.x, tid = threadIdx.x;
    float s = g_psum[(size_t)c * NSLOT + tid] + g_psum[(size_t)c * NSLOT + 256 + tid];
    float q = g_psq [(size_t)c * NSLOT + tid] + g_psq [(size_t)c * NSLOT + 256 + tid];
    __shared__ float rs[256], rq[256];
    rs[tid] = s; rq[tid] = q;
    __syncthreads();
    for (int o = 128; o > 0; o >>= 1) {
        if (tid < o) { rs[tid] += rs[tid + o]; rq[tid] += rq[tid + o]; }
        __syncthreads();
    }
    if (tid == 0) {
        float inv = 1.0f / (float)(BB * NP);
        float mean = rs[0] * inv;
        float var = rq[0] * inv - mean * mean;
        float a = gamma[c] * rsqrtf(var + BN_EPS);
        g_na[c] = a;
        g_nb[c] = beta[c] - mean * a;
    }
}

// ---------------- BN-apply, vectorized: tile 64c x 32n, 16B pair stores ----------
template <bool RES, bool WOUT, bool WBT>
__global__ void applyT_kernel(const __nv_bfloat16* __restrict__ Th,
                              const __nv_bfloat16* __restrict__ Tl,
                              __nv_bfloat16* __restrict__ Dh,
                              __nv_bfloat16* __restrict__ Dl,
                              float* __restrict__ O) {
    __shared__ float ts[64][33];
    __shared__ float t2[64][33];
    int b = blockIdx.z;
    int n0 = blockIdx.x * 32, c0 = blockIdx.y * 64;
    int tx = threadIdx.x, ty = threadIdx.y;   // 32 x 8
    // phase 1: BN in [c][n] (coalesced fp32 g_t read)
#pragma unroll
    for (int j = 0; j < 64; j += 8) {
        int c = c0 + ty + j;
        size_t off = ((size_t)b * COUT + c) * NP + n0 + tx;
        ts[ty + j][tx] = fmaf(g_na[c], g_t[off], g_nb[c]);
    }
    __syncthreads();
    // phase 2: [n][c] domain — 8 consecutive channels per thread, 16B accesses
    {
        int u = ty * 32 + tx;
        int n_l = u >> 3, cg = u & 7;
        size_t o = ((size_t)b * NP + n0 + n_l) * RS + c0 + cg * 8;
        float v[8];
#pragma unroll
        for (int i = 0; i < 8; i++) v[i] = ts[cg * 8 + i][n_l];
        if (RES) {
            uint4 rh = *(const uint4*)(Th + o);
            uint4 rl = *(const uint4*)(Tl + o);
            const __nv_bfloat16* ph = (const __nv_bfloat16*)&rh;
            const __nv_bfloat16* pl = (const __nv_bfloat16*)&rl;
#pragma unroll
            for (int i = 0; i < 8; i++)
                v[i] += __bfloat162float(ph[i]) + __bfloat162float(pl[i]);
        }
#pragma unroll
        for (int i = 0; i < 8; i++) v[i] = fmaxf(v[i], 0.f);
        if (WBT) {
            uint4 uh, ul;
            __nv_bfloat16* ph = (__nv_bfloat16*)&uh;
            __nv_bfloat16* pl = (__nv_bfloat16*)&ul;
#pragma unroll
            for (int i = 0; i < 8; i++) bf16_split(v[i], ph[i], pl[i]);
            *(uint4*)(Dh + o) = uh;
            *(uint4*)(Dl + o) = ul;
        }
        if (WOUT) {
#pragma unroll
            for (int i = 0; i < 8; i++) t2[cg * 8 + i][n_l] = v[i];
        }
    }
    if (WOUT) {
        __syncthreads();
#pragma unroll
        for (int j = 0; j < 64; j += 8)
            O[((size_t)b * COUT + c0 + ty + j) * NP + n0 + tx] = t2[ty + j][tx];
    }
}

// ---------------- launch ----------------
extern "C" void kernel_launch(void* const* d_in, const int* in_sizes, int n_in,
                              void* d_out, int out_size) {
    const float* xyz1    = (const float*)d_in[0];
    const float* xyz2    = (const float*)d_in[1];
    const float* points1 = (const float*)d_in[2];
    const float* points2 = (const float*)d_in[3];
    const float* fuse_W  = (const float*)d_in[4];
    const float* fuse_b  = (const float*)d_in[5];
    const float* fuse_g  = (const float*)d_in[6];
    const float* fuse_be = (const float*)d_in[7];
    const float* blk_W1  = (const float*)d_in[8];
    const float* blk_b1  = (const float*)d_in[9];
    const float* blk_g1  = (const float*)d_in[10];
    const float* blk_be1 = (const float*)d_in[11];
    const float* blk_W2  = (const float*)d_in[12];
    const float* blk_b2  = (const float*)d_in[13];
    const float* blk_g2  = (const float*)d_in[14];
    const float* blk_be2 = (const float*)d_in[15];
    float* out = (float*)d_out;

    void* pv;
    cudaGetSymbolAddress(&pv, g_wh);  __nv_bfloat16* wh = (__nv_bfloat16*)pv;
    cudaGetSymbolAddress(&pv, g_wl);  __nv_bfloat16* wl = (__nv_bfloat16*)pv;
    cudaGetSymbolAddress(&pv, g_bth); __nv_bfloat16* th = (__nv_bfloat16*)pv;
    cudaGetSymbolAddress(&pv, g_btl); __nv_bfloat16* tl = (__nv_bfloat16*)pv;
    cudaGetSymbolAddress(&pv, g_byh); __nv_bfloat16* yh = (__nv_bfloat16*)pv;
    cudaGetSymbolAddress(&pv, g_byl); __nv_bfloat16* yl = (__nv_bfloat16*)pv;

    const int SMEM_GEMM = 3 * (2 * BM * SST + 2 * BN * SST) * 2;  // 92160 B
    cudaFuncSetAttribute(gemm_mma_kernel<CIN>,  cudaFuncAttributeMaxDynamicSharedMemorySize, SMEM_GEMM);
    cudaFuncSetAttribute(gemm_mma_kernel<COUT>, cudaFuncAttributeMaxDynamicSharedMemorySize, SMEM_GEMM);

    dim3 ggrid(NP / BN, COUT / BM, BB);                 // (128, 2, 4)
    dim3 agrid(NP / 32, COUT / 64, BB);                 // (256, 4, 4)
    dim3 ablk(32, 8);

    convert_w_all_kernel<<<(WTOT + 255) / 256, 256>>>(fuse_W, blk_W1, blk_W2);
    transpose_p2_kernel<<<dim3(SP / 32, D2 / 32, BB), ablk>>>(points2);
    knn_kernel<<<dim3(NP / 128, BB), 128>>>(xyz1, xyz2);
    interp_kernel<<<dim3(NP / 32, BB), 256>>>();
    convert_p1_kernel<<<dim3(NP / 32, D1 / 32, BB), ablk>>>(points1);

    // fuse: 384 -> 256, BN, relu -> trunk bt
    gemm_mma_kernel<CIN><<<ggrid, 256, SMEM_GEMM>>>(wh, wl, th, tl, fuse_b);
    finalize_kernel<<<COUT, 256>>>(fuse_g, fuse_be);
    applyT_kernel<false, false, true><<<agrid, ablk>>>(nullptr, nullptr, th, tl, nullptr);

    for (int i = 0; i < 2; i++) {
        gemm_mma_kernel<COUT><<<ggrid, 256, SMEM_GEMM>>>(
            wh + OFF_W1 + (size_t)i * CC, wl + OFF_W1 + (size_t)i * CC,
            th, tl, blk_b1 + (size_t)i * COUT);
        finalize_kernel<<<COUT, 256>>>(blk_g1 + (size_t)i * COUT, blk_be1 + (size_t)i * COUT);
        applyT_kernel<false, false, true><<<agrid, ablk>>>(nullptr, nullptr, yh, yl, nullptr);

        gemm_mma_kernel<COUT><<<ggrid, 256, SMEM_GEMM>>>(
            wh + OFF_W2 + (size_t)i * CC, wl + OFF_W2 + (size_t)i * CC,
            yh, yl, blk_b2 + (size_t)i * COUT);
        finalize_kernel<<<COUT, 256>>>(blk_g2 + (size_t)i * COUT, blk_be2 + (size_t)i * COUT);
        if (i == 0)
            applyT_kernel<true, false, true><<<agrid, ablk>>>(th, tl, th, tl, nullptr);
        else
            applyT_kernel<true, true, false><<<agrid, ablk>>>(th, tl, nullptr, nullptr, out);
    }
}